// round 1
// baseline (speedup 1.0000x reference)
#include <cuda_runtime.h>
#include <cuda_bf16.h>
#include <cstdint>

#define STEPS  30
#define HIDDEN 32
#define NPAIR  (HIDDEN / 2)
#define TPB    128

// ---------- packed f32x2 helpers (Blackwell sm_100+) ----------
__device__ __forceinline__ unsigned long long pack2(float lo, float hi) {
    unsigned long long r;
    asm("mov.b64 %0, {%1, %2};" : "=l"(r) : "f"(lo), "f"(hi));
    return r;
}
__device__ __forceinline__ void unpack2(unsigned long long v, float& lo, float& hi) {
    asm("mov.b64 {%0, %1}, %2;" : "=f"(lo), "=f"(hi) : "l"(v));
}
__device__ __forceinline__ unsigned long long fma2(unsigned long long a,
                                                   unsigned long long b,
                                                   unsigned long long c) {
    unsigned long long d;
    asm("fma.rn.f32x2 %0, %1, %2, %3;" : "=l"(d) : "l"(a), "l"(b), "l"(c));
    return d;
}
__device__ __forceinline__ unsigned long long add2(unsigned long long a,
                                                   unsigned long long b) {
    unsigned long long d;
    asm("add.rn.f32x2 %0, %1, %2;" : "=l"(d) : "l"(a), "l"(b));
    return d;
}

__global__ void __launch_bounds__(TPB, 2)
rhm_kernel(const float* __restrict__ S,
           const float* __restrict__ W1,
           const float* __restrict__ b1,
           const float* __restrict__ W2,
           const float* __restrict__ b2,
           const float* __restrict__ a_init,
           float* __restrict__ out,
           int B)
{
    // One reused staging buffer: holds S rows on entry, d outputs on exit.
    // Stride 31 (coprime with 32) -> conflict-free per-step LDS/STS.
    __shared__ float sbuf[TPB][STEPS + 1];

    const int tid = threadIdx.x;
    const long long base = (long long)blockIdx.x * TPB;
    const int nvalid = (int)min((long long)TPB, (long long)B - base);   // elements in this CTA
    const int ntot   = nvalid * STEPS;

    // ---- coalesced stage-in of S ----
    {
        const float* Sblk = S + base * STEPS;
        #pragma unroll
        for (int k = 0; k < STEPS; ++k) {
            int i = k * TPB + tid;
            if (i < ntot) {
                int e  = i / STEPS;
                int st = i - e * STEPS;
                sbuf[e][st] = Sblk[i];
            }
        }
    }

    // ---- weights into register pairs (per-thread, broadcast LDG -> L1 hit) ----
    unsigned long long w0p[NPAIR], w1p[NPAIR], w2p[NPAIR], b1p[NPAIR], wop[NPAIR];
    {
        const float2* W1f2 = reinterpret_cast<const float2*>(W1);  // (3,32) row-major
        const float2* b1f2 = reinterpret_cast<const float2*>(b1);
        const float2* W2f2 = reinterpret_cast<const float2*>(W2);  // (32,1)
        #pragma unroll
        for (int j = 0; j < NPAIR; ++j) {
            float2 a = W1f2[j];              w0p[j] = pack2(a.x, a.y);   // W1[0][2j..]
            float2 bb = W1f2[NPAIR + j];     w1p[j] = pack2(bb.x, bb.y); // W1[1][2j..]
            float2 c = W1f2[2 * NPAIR + j];  w2p[j] = pack2(c.x, c.y);   // W1[2][2j..]
            float2 dd = b1f2[j];             b1p[j] = pack2(dd.x, dd.y);
            float2 e = W2f2[j];              wop[j] = pack2(e.x, e.y);
        }
    }
    const float bias2 = b2[0];

    float h = 0.0f;
    float d = a_init[0];

    __syncthreads();

    const bool active = (tid < nvalid);

    // ---- serial recurrence over time; hidden dim packed 2-wide ----
    #pragma unroll 1
    for (int t = 0; t < STEPS; ++t) {
        float s = active ? sbuf[tid][t] : 0.0f;
        unsigned long long s2 = pack2(s, s);
        unsigned long long d2 = pack2(d, d);
        unsigned long long h2 = pack2(h, h);

        unsigned long long acc[4] = {0ull, 0ull, 0ull, 0ull};  // bit pattern of (0.f,0.f)

        #pragma unroll
        for (int j = 0; j < NPAIR; ++j) {
            unsigned long long p = fma2(s2, w0p[j], b1p[j]);   // s*W1[0] + b1
            p = fma2(d2, w1p[j], p);                           // + d*W1[1]
            p = fma2(h2, w2p[j], p);                           // + h*W1[2]
            // ReLU on the (free) scalar halves -> alu pipe, off the fma pipe
            float lo, hi;
            unpack2(p, lo, hi);
            lo = fmaxf(lo, 0.0f);
            hi = fmaxf(hi, 0.0f);
            p = pack2(lo, hi);
            acc[j & 3] = fma2(p, wop[j], acc[j & 3]);          // dot with W2
        }

        unsigned long long accs = add2(add2(acc[0], acc[1]), add2(acc[2], acc[3]));
        float lo, hi;
        unpack2(accs, lo, hi);
        float dnew = lo + hi + bias2;

        h = 0.8f * h + 0.2f * dnew;
        d = dnew;
        if (active) sbuf[tid][t] = dnew;   // overwrite consumed s_t with output d_t
    }

    __syncthreads();

    // ---- coalesced flush of outputs ----
    {
        float* Oblk = out + base * STEPS;
        #pragma unroll
        for (int k = 0; k < STEPS; ++k) {
            int i = k * TPB + tid;
            if (i < ntot) {
                int e  = i / STEPS;
                int st = i - e * STEPS;
                Oblk[i] = sbuf[e][st];
            }
        }
    }
}

extern "C" void kernel_launch(void* const* d_in, const int* in_sizes, int n_in,
                              void* d_out, int out_size)
{
    const float* S      = (const float*)d_in[0];
    const float* W1     = (const float*)d_in[1];
    const float* b1     = (const float*)d_in[2];
    const float* W2     = (const float*)d_in[3];
    const float* b2     = (const float*)d_in[4];
    const float* a_init = (const float*)d_in[5];
    float* out = (float*)d_out;

    int B = in_sizes[0] / STEPS;
    int grid = (B + TPB - 1) / TPB;
    rhm_kernel<<<grid, TPB>>>(S, W1, b1, W2, b2, a_init, out, B);
}